// round 12
// baseline (speedup 1.0000x reference)
#include <cuda_runtime.h>
#include <math.h>

#define BATCH 4
#define C 32
#define HW 4096
#define LSEQ 4096
#define GTOT 16384
#define DIN 64
#define DST 32
#define CH 64
#define LC 64

// -------- device scratch --------
__device__ float  g_t   [BATCH*64*HW];
__device__ float  g_x2  [BATCH*C*HW];
__device__ float  g_Bm  [GTOT*DST];
__device__ float  g_Cm  [GTOT*DST];
__device__ float2 g_Pa  [GTOT*DIN];      // [b][d][l] {delta, delta*x}
__device__ float2 g_Pb  [GTOT*DIN];      // [b][d][l] {x*Dp, silu(z)}
__device__ float  g_ys  [GTOT*DIN];      // [b][d][l]
__device__ float  g_yimg[BATCH*C*HW];
__device__ float  g_cA   [BATCH*DIN*CH*DST];
__device__ float  g_cH   [BATCH*DIN*CH*DST];
__device__ float  g_hinit[BATCH*DIN*CH*DST];

__device__ __forceinline__ float warp_sum(float v) {
#pragma unroll
    for (int o = 16; o; o >>= 1) v += __shfl_xor_sync(0xffffffffu, v, o);
    return v;
}

// raw MUFU.EX2: 2^x
__device__ __forceinline__ float ex2(float x) {
    float r;
    asm("ex2.approx.ftz.f32 %0, %1;" : "=f"(r) : "f"(x));
    return r;
}

// ============================================================
// 3x3 conv, pad 1, direct. 32x32 tile/block, OCG oc per thread.
// Weights in smem, input tile double-buffered.
// ============================================================
template<int IC, int OC, int OCG, bool RELU, bool RES>
__global__ __launch_bounds__(256) void conv3x3_k(
    const float* __restrict__ in, const float* __restrict__ wt,
    const float* __restrict__ bias, const float* __restrict__ res,
    float* __restrict__ out)
{
    __shared__ float tile[2][34 * 35];
    __shared__ float sWt[OCG * IC * 9];
    const int tx = threadIdx.x, ty = threadIdx.y;
    const int tid = ty * 16 + tx;
    const int zb = blockIdx.z;
    const int b   = zb / (OC / OCG);
    const int oc0 = (zb % (OC / OCG)) * OCG;
    const int x0 = blockIdx.x * 32, y0 = blockIdx.y * 32;

    for (int i = tid; i < OCG * IC * 9; i += 256) sWt[i] = wt[oc0 * IC * 9 + i];

    int  off[5], si[5];
    bool vd[5], inb[5];
#pragma unroll
    for (int k = 0; k < 5; k++) {
        int i = tid + k * 256;
        inb[k] = i < 1156;
        int r = i / 34, c = i % 34;
        int yy = y0 + r - 1, xx = x0 + c - 1;
        vd[k] = inb[k] && (unsigned)yy < 64u && (unsigned)xx < 64u;
        off[k] = (yy << 6) + xx;
        si[k] = r * 35 + c;
    }

    float acc[OCG][2][2];
#pragma unroll
    for (int j = 0; j < OCG; j++) {
        float bv = bias[oc0 + j];
#pragma unroll
        for (int pr = 0; pr < 2; pr++)
#pragma unroll
            for (int pc = 0; pc < 2; pc++) acc[j][pr][pc] = bv;
    }

    const float* ip0 = in + ((long)(b * IC) << 12);
#pragma unroll
    for (int k = 0; k < 5; k++)
        if (inb[k]) tile[0][si[k]] = vd[k] ? ip0[off[k]] : 0.f;
    __syncthreads();

    for (int ic = 0; ic < IC; ic++) {
        float pf[5];
        if (ic + 1 < IC) {
            const float* ipn = ip0 + ((long)(ic + 1) << 12);
#pragma unroll
            for (int k = 0; k < 5; k++) pf[k] = vd[k] ? ipn[off[k]] : 0.f;
        }
        const float* tb = tile[ic & 1];
        float dr[4][4];
#pragma unroll
        for (int r = 0; r < 4; r++)
#pragma unroll
            for (int c = 0; c < 4; c++) dr[r][c] = tb[(ty * 2 + r) * 35 + tx * 2 + c];
#pragma unroll
        for (int j = 0; j < OCG; j++) {
            const float* wp = sWt + (j * IC + ic) * 9;
#pragma unroll
            for (int ky = 0; ky < 3; ky++)
#pragma unroll
                for (int kx = 0; kx < 3; kx++) {
                    float wv = wp[ky * 3 + kx];
#pragma unroll
                    for (int pr = 0; pr < 2; pr++)
#pragma unroll
                        for (int pc = 0; pc < 2; pc++)
                            acc[j][pr][pc] = fmaf(dr[pr + ky][pc + kx], wv, acc[j][pr][pc]);
                }
        }
        if (ic + 1 < IC) {
            float* tn = tile[(ic + 1) & 1];
#pragma unroll
            for (int k = 0; k < 5; k++)
                if (inb[k]) tn[si[k]] = pf[k];
            __syncthreads();
        }
    }

#pragma unroll
    for (int j = 0; j < OCG; j++) {
        int oc = oc0 + j;
#pragma unroll
        for (int pr = 0; pr < 2; pr++)
#pragma unroll
            for (int pc = 0; pc < 2; pc++) {
                int y = y0 + ty * 2 + pr, x = x0 + tx * 2 + pc;
                float v = acc[j][pr][pc];
                if (RELU) v = fmaxf(v, 0.f);
                long o = ((long)(b * OC + oc) << 12) + (y << 6) + x;
                if (RES) v += res[o];
                out[o] = v;
            }
    }
}

// ============================================================
// big_k: LN + in_proj + conv1d/silu + x_proj + softplus + P pack
// 512 threads; block = 64 seq rows; 3-row halo recomputed in-block.
// ============================================================
#define BIG_SMEM_FLOATS 24476
__global__ __launch_bounds__(512) void big_k(
    const float* __restrict__ x2, const float* __restrict__ lg,
    const float* __restrict__ lb_, const float* __restrict__ Win,
    const float* __restrict__ w1, const float* __restrict__ b1,
    const float* __restrict__ xw,
    const float* __restrict__ dtw, const float* __restrict__ dtb,
    const float* __restrict__ Dp,
    float* __restrict__ Bm, float* __restrict__ Cm,
    float2* __restrict__ Pa, float2* __restrict__ Pb)
{
    extern __shared__ float sm[];
    float* sA   = sm;
    float* sWin = sm + 2448;
    float* sXm  = sm + 7056;
    float* sZ   = sm + 11612;
    float* sWx  = sm + 15772;
    float* sXm2 = sm + 19996;
    float* sDt  = sm + 24348;
    const int g0 = blockIdx.x * 64;
    const int tid = threadIdx.x;
    const int warp = tid >> 5, lane = tid & 31;
    const int b = g0 >> 12;
    const int lb = g0 & 4095;

    for (int i = tid; i < 128 * 32; i += 512) sWin[(i >> 5) * 36 + (i & 31)] = Win[i];
    for (int i = tid; i < 66 * 16; i += 512) ((float4*)sWx)[i] = ((const float4*)xw)[i];

    // LN rows hr=0..66 (global row g0+hr-3)
    for (int hr = warp; hr < 67; hr += 16) {
        bool valid = (lb + hr) >= 3;
        float v = valid ? x2[(g0 + hr - 3) * 32 + lane] : 0.f;
        float s = warp_sum(v);
        float mu = s * (1.f / 32.f);
        float d = v - mu;
        float q = warp_sum(d * d);
        sA[hr * 36 + lane] = d * rsqrtf(q * (1.f / 32.f) + 1e-5f) * lg[lane] + lb_[lane];
    }
    __syncthreads();

    // GEMM1 main: rows 0..63, cols 0..127; tile 2x8, 512 threads
    {
        const int rg = tid & 31, cg = tid >> 5;
        const int r0 = rg * 2, c0 = cg * 8;
        float acc[2][8];
#pragma unroll
        for (int j = 0; j < 2; j++)
#pragma unroll
            for (int i = 0; i < 8; i++) acc[j][i] = 0.f;
#pragma unroll
        for (int k0 = 0; k0 < 32; k0 += 4) {
            float4 a4[2], w4[8];
#pragma unroll
            for (int j = 0; j < 2; j++) a4[j] = *(const float4*)&sA[(3 + r0 + j) * 36 + k0];
#pragma unroll
            for (int i = 0; i < 8; i++) w4[i] = *(const float4*)&sWin[(c0 + i) * 36 + k0];
#pragma unroll
            for (int j = 0; j < 2; j++)
#pragma unroll
                for (int i = 0; i < 8; i++) {
                    acc[j][i] = fmaf(a4[j].x, w4[i].x, acc[j][i]);
                    acc[j][i] = fmaf(a4[j].y, w4[i].y, acc[j][i]);
                    acc[j][i] = fmaf(a4[j].z, w4[i].z, acc[j][i]);
                    acc[j][i] = fmaf(a4[j].w, w4[i].w, acc[j][i]);
                }
        }
#pragma unroll
        for (int j = 0; j < 2; j++) {
            int r = r0 + j;
#pragma unroll
            for (int i = 0; i < 8; i++) {
                int c = c0 + i;
                if (c < 64) sXm[(3 + r) * 68 + c] = acc[j][i];
                else        sZ[r * 65 + (c - 64)] = acc[j][i];
            }
        }
    }
    // GEMM1 halo: rows hr=0..2, xm cols only
    if (tid < 192) {
        int r = tid >> 6, c = tid & 63;
        float s = 0.f;
#pragma unroll
        for (int k = 0; k < 32; k++) s = fmaf(sA[r * 36 + k], sWin[c * 36 + k], s);
        sXm[r * 68 + c] = s;
    }
    __syncthreads();

    // conv1d + silu
    for (int i = tid; i < 64 * 64; i += 512) {
        int d = i & 63, r = i >> 6;
        float acc = __ldg(&b1[d]);
#pragma unroll
        for (int k = 0; k < 4; k++) {
            float v = ((lb + r + k) >= 3) ? sXm[(r + k) * 68 + d] : 0.f;
            acc = fmaf(__ldg(&w1[d * 4 + k]), v, acc);
        }
        sXm2[r * 68 + d] = acc * __fdividef(1.f, 1.f + __expf(-acc));
    }
    __syncthreads();

    // GEMM2 x_proj: tile 2x8, 288 threads
    if (tid < 288) {
        const int rg = tid & 31, cg = tid >> 5;
        const int r0 = rg * 2, c0 = cg * 8;
        float acc[2][8];
#pragma unroll
        for (int j = 0; j < 2; j++)
#pragma unroll
            for (int i = 0; i < 8; i++) acc[j][i] = 0.f;
#pragma unroll 4
        for (int k0 = 0; k0 < 64; k0 += 4) {
            float4 a4[2], w4[8];
#pragma unroll
            for (int j = 0; j < 2; j++) a4[j] = *(const float4*)&sXm2[(r0 + j) * 68 + k0];
#pragma unroll
            for (int i = 0; i < 8; i++) {
                int c = c0 + i; if (c > 65) c = 65;
                w4[i] = *(const float4*)&sWx[c * 64 + k0];
            }
#pragma unroll
            for (int j = 0; j < 2; j++)
#pragma unroll
                for (int i = 0; i < 8; i++) {
                    acc[j][i] = fmaf(a4[j].x, w4[i].x, acc[j][i]);
                    acc[j][i] = fmaf(a4[j].y, w4[i].y, acc[j][i]);
                    acc[j][i] = fmaf(a4[j].z, w4[i].z, acc[j][i]);
                    acc[j][i] = fmaf(a4[j].w, w4[i].w, acc[j][i]);
                }
        }
#pragma unroll
        for (int j = 0; j < 2; j++) {
            int r = r0 + j, g = g0 + r;
#pragma unroll
            for (int i = 0; i < 8; i++) {
                int c = c0 + i;
                float v = acc[j][i];
                if (c < 2)       sDt[r * 2 + c] = v;
                else if (c < 34) Bm[g * 32 + c - 2] = v;
                else if (c < 66) Cm[g * 32 + c - 34] = v;
            }
        }
    }
    __syncthreads();

    // epilogue: softplus + P packing (Pa.x = delta)
    const int l = tid & 63, dg = tid >> 6;
    const float dt0 = sDt[l * 2], dt1 = sDt[l * 2 + 1];
#pragma unroll
    for (int j = 0; j < 8; j++) {
        int d = dg * 8 + j;
        float t = fmaf(dt0, __ldg(&dtw[d * 2]), fmaf(dt1, __ldg(&dtw[d * 2 + 1]), __ldg(&dtb[d])));
        float delta = (t > 20.f) ? t : log1pf(__expf(t));
        float xv = sXm2[l * 68 + d];
        float zv = sZ[l * 65 + d];
        long pbase = ((long)(b * 64 + d) << 12) + lb + l;
        Pa[pbase] = make_float2(delta, delta * xv);
        Pb[pbase] = make_float2(xv * __ldg(&Dp[d]), zv * __fdividef(1.f, 1.f + __expf(-zv)));
    }
}

// ============================================================
// chunked scan pass 1: warp per (b,d,chunk); dA via MUFU EX2
// ============================================================
__global__ __launch_bounds__(256) void scan1_k(
    const float2* __restrict__ Pa, const float* __restrict__ Bm,
    const float* __restrict__ Alog,
    float* __restrict__ cA, float* __restrict__ cH)
{
    int warp = (blockIdx.x * blockDim.x + threadIdx.x) >> 5;
    int lane = threadIdx.x & 31;
    int ch = warp & (CH - 1);
    int d  = (warp >> 6) & (DIN - 1);
    int b  = warp >> 12;
    float aln = -__expf(Alog[d * 32 + lane]) * 1.4426950408889634f;
    const float2* Pp = Pa + ((long)(b * 64 + d) << 12) + ch * LC;
    const float*  Bp = Bm + ((long)((b << 12) + ch * LC) << 5) + lane;
    float h = 0.f, ap = 1.f;
#pragma unroll 8
    for (int l = 0; l < LC; l++) {
        float2 p = Pp[l];
        float bv = Bp[l << 5];
        float dA = ex2(p.x * aln);
        ap *= dA;
        h = fmaf(h, dA, p.y * bv);
    }
    int idx = (warp << 5) + lane;
    cA[idx] = ap;
    cH[idx] = h;
}

// pass 2: sequential combine over chunks (warp per (b,d))
__global__ __launch_bounds__(256) void scan2_k(
    const float* __restrict__ cA, const float* __restrict__ cH,
    float* __restrict__ hinit)
{
    int warp = (blockIdx.x * blockDim.x + threadIdx.x) >> 5;
    int lane = threadIdx.x & 31;
    int base = warp << 11;
    float h = 0.f;
#pragma unroll 8
    for (int ch = 0; ch < CH; ch++) {
        int idx = base + (ch << 5) + lane;
        float ap = cA[idx];
        float hl = cH[idx];
        hinit[idx] = h;
        h = fmaf(h, ap, hl);
    }
}

// ============================================================
// pass 3: warp per (b,d,chunk); deferred smem reduction.
// ============================================================
__global__ __launch_bounds__(256) void scan3_k(
    const float2* __restrict__ Pa, const float2* __restrict__ Pb,
    const float* __restrict__ Bm, const float* __restrict__ Cm,
    const float* __restrict__ Alog, const float* __restrict__ hinit,
    float* __restrict__ ys)
{
    __shared__ float sP[8][32 * 33];
    int warp = (blockIdx.x * blockDim.x + threadIdx.x) >> 5;
    int wl = (threadIdx.x >> 5);
    int lane = threadIdx.x & 31;
    int ch = warp & (CH - 1);
    int d  = (warp >> 6) & (DIN - 1);
    int b  = warp >> 12;
    float aln = -__expf(Alog[d * 32 + lane]) * 1.4426950408889634f;
    long pbase = ((long)(b * 64 + d) << 12) + ch * LC;
    const float2* PaP = Pa + pbase;
    const float2* PbP = Pb + pbase;
    const float*  Bp = Bm + ((long)((b << 12) + ch * LC) << 5) + lane;
    const float*  Cp = Cm + ((long)((b << 12) + ch * LC) << 5) + lane;
    float h = hinit[(warp << 5) + lane];
    float* sp = sP[wl];
#pragma unroll
    for (int half = 0; half < 2; half++) {
#pragma unroll
        for (int j = 0; j < 32; j++) {
            int l = half * 32 + j;
            float2 pa = PaP[l];
            float bv = Bp[l << 5];
            float cv = Cp[l << 5];
            float dA = ex2(pa.x * aln);
            h = fmaf(h, dA, pa.y * bv);
            sp[j * 33 + lane] = h * cv;
        }
        __syncwarp();
        float pr = 0.f;
#pragma unroll
        for (int k = 0; k < 32; k++) pr += sp[lane * 33 + k];
        float2 pb = PbP[half * 32 + lane];
        ys[pbase + half * 32 + lane] = (pr + pb.x) * pb.y;
        __syncwarp();
    }
}

// ============================================================
// out_proj: reads ys [b][d][l], writes yimg (b,c,hw)
// ============================================================
__global__ __launch_bounds__(256) void outproj_k(
    const float* __restrict__ ys, const float* __restrict__ Wo,
    float* __restrict__ oimg)
{
    __shared__ float sA[64 * 68];
    __shared__ float sW[32 * 68];
    const int g0 = blockIdx.x * 64;
    const int tid = threadIdx.x;
    const int b = g0 >> 12;
    const int lb = g0 & 4095;

    for (int i = tid; i < 64 * 64; i += 256) {
        int d = i >> 6, l = i & 63;
        sA[l * 68 + d] = ys[((long)(b * 64 + d) << 12) + lb + l];
    }
    for (int i = tid; i < 32 * 64; i += 256) {
        int c = i >> 6, k = i & 63;
        sW[c * 68 + k] = Wo[i];
    }
    __syncthreads();

    const int rg = tid & 31, cg = tid >> 5;
    const int r0 = rg * 2, c0 = cg * 4;
    float acc[2][4];
#pragma unroll
    for (int j = 0; j < 2; j++)
#pragma unroll
        for (int i = 0; i < 4; i++) acc[j][i] = 0.f;
#pragma unroll 4
    for (int k0 = 0; k0 < 64; k0 += 4) {
        float4 a4[2], w4[4];
#pragma unroll
        for (int j = 0; j < 2; j++) a4[j] = *(const float4*)&sA[(r0 + j) * 68 + k0];
#pragma unroll
        for (int i = 0; i < 4; i++) w4[i] = *(const float4*)&sW[(c0 + i) * 68 + k0];
#pragma unroll
        for (int j = 0; j < 2; j++)
#pragma unroll
            for (int i = 0; i < 4; i++) {
                acc[j][i] = fmaf(a4[j].x, w4[i].x, acc[j][i]);
                acc[j][i] = fmaf(a4[j].y, w4[i].y, acc[j][i]);
                acc[j][i] = fmaf(a4[j].z, w4[i].z, acc[j][i]);
                acc[j][i] = fmaf(a4[j].w, w4[i].w, acc[j][i]);
            }
    }
#pragma unroll
    for (int i = 0; i < 4; i++) {
        int c = c0 + i;
#pragma unroll
        for (int j = 0; j < 2; j++)
            oimg[((long)(b * 32 + c) << 12) + lb + r0 + j] = acc[j][i];
    }
}

// ============================================================
extern "C" void kernel_launch(void* const* d_in, const int* in_sizes, int n_in,
                              void* d_out, int out_size)
{
    const float* x        = (const float*)d_in[0];
    const float* conv1_w  = (const float*)d_in[1];
    const float* conv1_b  = (const float*)d_in[2];
    const float* conv2_w  = (const float*)d_in[3];
    const float* conv2_b  = (const float*)d_in[4];
    const float* ln_g     = (const float*)d_in[5];
    const float* ln_b     = (const float*)d_in[6];
    const float* in_proj_w= (const float*)d_in[7];
    const float* conv1d_w = (const float*)d_in[8];
    const float* conv1d_b = (const float*)d_in[9];
    const float* x_proj_w = (const float*)d_in[10];
    const float* dt_proj_w= (const float*)d_in[11];
    const float* dt_proj_b= (const float*)d_in[12];
    const float* A_log    = (const float*)d_in[13];
    const float* Dp       = (const float*)d_in[14];
    const float* out_proj_w=(const float*)d_in[15];
    const float* smooth_w = (const float*)d_in[16];
    const float* smooth_b = (const float*)d_in[17];
    float* out = (float*)d_out;

    float  *t_, *x2_, *B_, *C_, *ys_, *yimg_, *cA_, *cH_, *hinit_;
    float2 *Pa_, *Pb_;
    cudaGetSymbolAddress((void**)&t_,   g_t);
    cudaGetSymbolAddress((void**)&x2_,  g_x2);
    cudaGetSymbolAddress((void**)&B_,   g_Bm);
    cudaGetSymbolAddress((void**)&C_,   g_Cm);
    cudaGetSymbolAddress((void**)&Pa_,  g_Pa);
    cudaGetSymbolAddress((void**)&Pb_,  g_Pb);
    cudaGetSymbolAddress((void**)&ys_,  g_ys);
    cudaGetSymbolAddress((void**)&yimg_,g_yimg);
    cudaGetSymbolAddress((void**)&cA_,  g_cA);
    cudaGetSymbolAddress((void**)&cH_,  g_cH);
    cudaGetSymbolAddress((void**)&hinit_, g_hinit);

    cudaFuncSetAttribute(big_k, cudaFuncAttributeMaxDynamicSharedMemorySize,
                         BIG_SMEM_FLOATS * 4);

    dim3 thr2d(16, 16);
    // more blocks per conv: OCG halved -> 512 blocks each (~3.5/SM)
    conv3x3_k<32, 64, 2, true, false><<<dim3(2, 2, BATCH * 32), thr2d>>>(x, conv1_w, conv1_b, nullptr, t_);
    conv3x3_k<64, 32, 1, false, true><<<dim3(2, 2, BATCH * 32), thr2d>>>(t_, conv2_w, conv2_b, x, x2_);
    big_k<<<GTOT / 64, 512, BIG_SMEM_FLOATS * 4>>>(x2_, ln_g, ln_b, in_proj_w,
        conv1d_w, conv1d_b, x_proj_w, dt_proj_w, dt_proj_b, Dp, B_, C_, Pa_, Pb_);
    scan1_k<<<BATCH * DIN * CH / 8, 256>>>(Pa_, B_, A_log, cA_, cH_);
    scan2_k<<<BATCH * DIN / 8, 256>>>(cA_, cH_, hinit_);
    scan3_k<<<BATCH * DIN * CH / 8, 256>>>(Pa_, Pb_, B_, C_, A_log, hinit_, ys_);
    outproj_k<<<GTOT / 64, 256>>>(ys_, out_proj_w, yimg_);
    conv3x3_k<32, 32, 1, false, false><<<dim3(2, 2, BATCH * 32), thr2d>>>(yimg_, smooth_w, smooth_b, nullptr, out);
}

// round 13
// speedup vs baseline: 1.1881x; 1.1881x over previous
#include <cuda_runtime.h>
#include <math.h>

#define BATCH 4
#define C 32
#define HW 4096
#define LSEQ 4096
#define GTOT 16384
#define DIN 64
#define DST 32
#define CH 64
#define LC 64

// -------- device scratch --------
__device__ float  g_t   [BATCH*64*HW];
__device__ float  g_x2  [BATCH*C*HW];
__device__ float  g_Bm  [GTOT*DST];
__device__ float  g_Cm  [GTOT*DST];
__device__ float2 g_Pa  [GTOT*DIN];      // [b][d][l] {delta, delta*x}
__device__ float2 g_Pb  [GTOT*DIN];      // [b][d][l] {x*Dp, silu(z)}
__device__ float  g_ys  [GTOT*DIN];      // [b][d][l]
__device__ float  g_yimg[BATCH*C*HW];
__device__ float  g_cA   [BATCH*DIN*CH*DST];
__device__ float  g_cH   [BATCH*DIN*CH*DST];
__device__ float  g_hinit[BATCH*DIN*CH*DST];

__device__ __forceinline__ float warp_sum(float v) {
#pragma unroll
    for (int o = 16; o; o >>= 1) v += __shfl_xor_sync(0xffffffffu, v, o);
    return v;
}

// raw MUFU.EX2: 2^x
__device__ __forceinline__ float ex2(float x) {
    float r;
    asm("ex2.approx.ftz.f32 %0, %1;" : "=f"(r) : "f"(x));
    return r;
}

// ============================================================
// 3x3 conv, pad 1, direct. 32x32 tile/block, OCG oc per thread.
// Weights in smem, input tile double-buffered. (R10 config)
// ============================================================
template<int IC, int OC, int OCG, bool RELU, bool RES>
__global__ __launch_bounds__(256) void conv3x3_k(
    const float* __restrict__ in, const float* __restrict__ wt,
    const float* __restrict__ bias, const float* __restrict__ res,
    float* __restrict__ out)
{
    __shared__ float tile[2][34 * 35];
    __shared__ float sWt[OCG * IC * 9];
    const int tx = threadIdx.x, ty = threadIdx.y;
    const int tid = ty * 16 + tx;
    const int zb = blockIdx.z;
    const int b   = zb / (OC / OCG);
    const int oc0 = (zb % (OC / OCG)) * OCG;
    const int x0 = blockIdx.x * 32, y0 = blockIdx.y * 32;

    for (int i = tid; i < OCG * IC * 9; i += 256) sWt[i] = wt[oc0 * IC * 9 + i];

    int  off[5], si[5];
    bool vd[5], inb[5];
#pragma unroll
    for (int k = 0; k < 5; k++) {
        int i = tid + k * 256;
        inb[k] = i < 1156;
        int r = i / 34, c = i % 34;
        int yy = y0 + r - 1, xx = x0 + c - 1;
        vd[k] = inb[k] && (unsigned)yy < 64u && (unsigned)xx < 64u;
        off[k] = (yy << 6) + xx;
        si[k] = r * 35 + c;
    }

    float acc[OCG][2][2];
#pragma unroll
    for (int j = 0; j < OCG; j++) {
        float bv = bias[oc0 + j];
#pragma unroll
        for (int pr = 0; pr < 2; pr++)
#pragma unroll
            for (int pc = 0; pc < 2; pc++) acc[j][pr][pc] = bv;
    }

    const float* ip0 = in + ((long)(b * IC) << 12);
#pragma unroll
    for (int k = 0; k < 5; k++)
        if (inb[k]) tile[0][si[k]] = vd[k] ? ip0[off[k]] : 0.f;
    __syncthreads();

    for (int ic = 0; ic < IC; ic++) {
        float pf[5];
        if (ic + 1 < IC) {
            const float* ipn = ip0 + ((long)(ic + 1) << 12);
#pragma unroll
            for (int k = 0; k < 5; k++) pf[k] = vd[k] ? ipn[off[k]] : 0.f;
        }
        const float* tb = tile[ic & 1];
        float dr[4][4];
#pragma unroll
        for (int r = 0; r < 4; r++)
#pragma unroll
            for (int c = 0; c < 4; c++) dr[r][c] = tb[(ty * 2 + r) * 35 + tx * 2 + c];
#pragma unroll
        for (int j = 0; j < OCG; j++) {
            const float* wp = sWt + (j * IC + ic) * 9;
#pragma unroll
            for (int ky = 0; ky < 3; ky++)
#pragma unroll
                for (int kx = 0; kx < 3; kx++) {
                    float wv = wp[ky * 3 + kx];
#pragma unroll
                    for (int pr = 0; pr < 2; pr++)
#pragma unroll
                        for (int pc = 0; pc < 2; pc++)
                            acc[j][pr][pc] = fmaf(dr[pr + ky][pc + kx], wv, acc[j][pr][pc]);
                }
        }
        if (ic + 1 < IC) {
            float* tn = tile[(ic + 1) & 1];
#pragma unroll
            for (int k = 0; k < 5; k++)
                if (inb[k]) tn[si[k]] = pf[k];
            __syncthreads();
        }
    }

#pragma unroll
    for (int j = 0; j < OCG; j++) {
        int oc = oc0 + j;
#pragma unroll
        for (int pr = 0; pr < 2; pr++)
#pragma unroll
            for (int pc = 0; pc < 2; pc++) {
                int y = y0 + ty * 2 + pr, x = x0 + tx * 2 + pc;
                float v = acc[j][pr][pc];
                if (RELU) v = fmaxf(v, 0.f);
                long o = ((long)(b * OC + oc) << 12) + (y << 6) + x;
                if (RES) v += res[o];
                out[o] = v;
            }
    }
}

// ============================================================
// big_k: LN + in_proj + conv1d/silu + x_proj + softplus + P pack
// 512 threads; block = 64 seq rows; 3-row halo recomputed in-block.
// ============================================================
#define BIG_SMEM_FLOATS 24476
__global__ __launch_bounds__(512) void big_k(
    const float* __restrict__ x2, const float* __restrict__ lg,
    const float* __restrict__ lb_, const float* __restrict__ Win,
    const float* __restrict__ w1, const float* __restrict__ b1,
    const float* __restrict__ xw,
    const float* __restrict__ dtw, const float* __restrict__ dtb,
    const float* __restrict__ Dp,
    float* __restrict__ Bm, float* __restrict__ Cm,
    float2* __restrict__ Pa, float2* __restrict__ Pb)
{
    extern __shared__ float sm[];
    float* sA   = sm;
    float* sWin = sm + 2448;
    float* sXm  = sm + 7056;
    float* sZ   = sm + 11612;
    float* sWx  = sm + 15772;
    float* sXm2 = sm + 19996;
    float* sDt  = sm + 24348;
    const int g0 = blockIdx.x * 64;
    const int tid = threadIdx.x;
    const int warp = tid >> 5, lane = tid & 31;
    const int b = g0 >> 12;
    const int lb = g0 & 4095;

    for (int i = tid; i < 128 * 32; i += 512) sWin[(i >> 5) * 36 + (i & 31)] = Win[i];
    for (int i = tid; i < 66 * 16; i += 512) ((float4*)sWx)[i] = ((const float4*)xw)[i];

    // LN rows hr=0..66 (global row g0+hr-3)
    for (int hr = warp; hr < 67; hr += 16) {
        bool valid = (lb + hr) >= 3;
        float v = valid ? x2[(g0 + hr - 3) * 32 + lane] : 0.f;
        float s = warp_sum(v);
        float mu = s * (1.f / 32.f);
        float d = v - mu;
        float q = warp_sum(d * d);
        sA[hr * 36 + lane] = d * rsqrtf(q * (1.f / 32.f) + 1e-5f) * lg[lane] + lb_[lane];
    }
    __syncthreads();

    // GEMM1 main: rows 0..63, cols 0..127; tile 2x8, 512 threads
    {
        const int rg = tid & 31, cg = tid >> 5;
        const int r0 = rg * 2, c0 = cg * 8;
        float acc[2][8];
#pragma unroll
        for (int j = 0; j < 2; j++)
#pragma unroll
            for (int i = 0; i < 8; i++) acc[j][i] = 0.f;
#pragma unroll
        for (int k0 = 0; k0 < 32; k0 += 4) {
            float4 a4[2], w4[8];
#pragma unroll
            for (int j = 0; j < 2; j++) a4[j] = *(const float4*)&sA[(3 + r0 + j) * 36 + k0];
#pragma unroll
            for (int i = 0; i < 8; i++) w4[i] = *(const float4*)&sWin[(c0 + i) * 36 + k0];
#pragma unroll
            for (int j = 0; j < 2; j++)
#pragma unroll
                for (int i = 0; i < 8; i++) {
                    acc[j][i] = fmaf(a4[j].x, w4[i].x, acc[j][i]);
                    acc[j][i] = fmaf(a4[j].y, w4[i].y, acc[j][i]);
                    acc[j][i] = fmaf(a4[j].z, w4[i].z, acc[j][i]);
                    acc[j][i] = fmaf(a4[j].w, w4[i].w, acc[j][i]);
                }
        }
#pragma unroll
        for (int j = 0; j < 2; j++) {
            int r = r0 + j;
#pragma unroll
            for (int i = 0; i < 8; i++) {
                int c = c0 + i;
                if (c < 64) sXm[(3 + r) * 68 + c] = acc[j][i];
                else        sZ[r * 65 + (c - 64)] = acc[j][i];
            }
        }
    }
    // GEMM1 halo: rows hr=0..2, xm cols only
    if (tid < 192) {
        int r = tid >> 6, c = tid & 63;
        float s = 0.f;
#pragma unroll
        for (int k = 0; k < 32; k++) s = fmaf(sA[r * 36 + k], sWin[c * 36 + k], s);
        sXm[r * 68 + c] = s;
    }
    __syncthreads();

    // conv1d + silu
    for (int i = tid; i < 64 * 64; i += 512) {
        int d = i & 63, r = i >> 6;
        float acc = __ldg(&b1[d]);
#pragma unroll
        for (int k = 0; k < 4; k++) {
            float v = ((lb + r + k) >= 3) ? sXm[(r + k) * 68 + d] : 0.f;
            acc = fmaf(__ldg(&w1[d * 4 + k]), v, acc);
        }
        sXm2[r * 68 + d] = acc * __fdividef(1.f, 1.f + __expf(-acc));
    }
    __syncthreads();

    // GEMM2 x_proj: tile 2x8, 288 threads
    if (tid < 288) {
        const int rg = tid & 31, cg = tid >> 5;
        const int r0 = rg * 2, c0 = cg * 8;
        float acc[2][8];
#pragma unroll
        for (int j = 0; j < 2; j++)
#pragma unroll
            for (int i = 0; i < 8; i++) acc[j][i] = 0.f;
#pragma unroll 4
        for (int k0 = 0; k0 < 64; k0 += 4) {
            float4 a4[2], w4[8];
#pragma unroll
            for (int j = 0; j < 2; j++) a4[j] = *(const float4*)&sXm2[(r0 + j) * 68 + k0];
#pragma unroll
            for (int i = 0; i < 8; i++) {
                int c = c0 + i; if (c > 65) c = 65;
                w4[i] = *(const float4*)&sWx[c * 64 + k0];
            }
#pragma unroll
            for (int j = 0; j < 2; j++)
#pragma unroll
                for (int i = 0; i < 8; i++) {
                    acc[j][i] = fmaf(a4[j].x, w4[i].x, acc[j][i]);
                    acc[j][i] = fmaf(a4[j].y, w4[i].y, acc[j][i]);
                    acc[j][i] = fmaf(a4[j].z, w4[i].z, acc[j][i]);
                    acc[j][i] = fmaf(a4[j].w, w4[i].w, acc[j][i]);
                }
        }
#pragma unroll
        for (int j = 0; j < 2; j++) {
            int r = r0 + j, g = g0 + r;
#pragma unroll
            for (int i = 0; i < 8; i++) {
                int c = c0 + i;
                float v = acc[j][i];
                if (c < 2)       sDt[r * 2 + c] = v;
                else if (c < 34) Bm[g * 32 + c - 2] = v;
                else if (c < 66) Cm[g * 32 + c - 34] = v;
            }
        }
    }
    __syncthreads();

    // epilogue: softplus + P packing (Pa.x = delta)
    const int l = tid & 63, dg = tid >> 6;
    const float dt0 = sDt[l * 2], dt1 = sDt[l * 2 + 1];
#pragma unroll
    for (int j = 0; j < 8; j++) {
        int d = dg * 8 + j;
        float t = fmaf(dt0, __ldg(&dtw[d * 2]), fmaf(dt1, __ldg(&dtw[d * 2 + 1]), __ldg(&dtb[d])));
        float delta = (t > 20.f) ? t : log1pf(__expf(t));
        float xv = sXm2[l * 68 + d];
        float zv = sZ[l * 65 + d];
        long pbase = ((long)(b * 64 + d) << 12) + lb + l;
        Pa[pbase] = make_float2(delta, delta * xv);
        Pb[pbase] = make_float2(xv * __ldg(&Dp[d]), zv * __fdividef(1.f, 1.f + __expf(-zv)));
    }
}

// ============================================================
// chunked scan pass 1: warp per (b,d,chunk); Pa read as float4
// ============================================================
__global__ __launch_bounds__(256) void scan1_k(
    const float2* __restrict__ Pa, const float* __restrict__ Bm,
    const float* __restrict__ Alog,
    float* __restrict__ cA, float* __restrict__ cH)
{
    int warp = (blockIdx.x * blockDim.x + threadIdx.x) >> 5;
    int lane = threadIdx.x & 31;
    int ch = warp & (CH - 1);
    int d  = (warp >> 6) & (DIN - 1);
    int b  = warp >> 12;
    float aln = -__expf(Alog[d * 32 + lane]) * 1.4426950408889634f;
    const float4* Pp4 = (const float4*)(Pa + ((long)(b * 64 + d) << 12) + ch * LC);
    const float*  Bp = Bm + ((long)((b << 12) + ch * LC) << 5) + lane;
    float h = 0.f, ap = 1.f;
#pragma unroll 4
    for (int l2 = 0; l2 < LC / 2; l2++) {
        float4 p = Pp4[l2];
        float bv0 = Bp[(2 * l2) << 5];
        float bv1 = Bp[(2 * l2 + 1) << 5];
        float dA0 = ex2(p.x * aln);
        ap *= dA0;
        h = fmaf(h, dA0, p.y * bv0);
        float dA1 = ex2(p.z * aln);
        ap *= dA1;
        h = fmaf(h, dA1, p.w * bv1);
    }
    int idx = (warp << 5) + lane;
    cA[idx] = ap;
    cH[idx] = h;
}

// pass 2: sequential combine over chunks (warp per (b,d))
__global__ __launch_bounds__(256) void scan2_k(
    const float* __restrict__ cA, const float* __restrict__ cH,
    float* __restrict__ hinit)
{
    int warp = (blockIdx.x * blockDim.x + threadIdx.x) >> 5;
    int lane = threadIdx.x & 31;
    int base = warp << 11;
    float h = 0.f;
#pragma unroll 8
    for (int ch = 0; ch < CH; ch++) {
        int idx = base + (ch << 5) + lane;
        float ap = cA[idx];
        float hl = cH[idx];
        hinit[idx] = h;
        h = fmaf(h, ap, hl);
    }
}

// ============================================================
// pass 3: warp per (b,d,chunk); Pa float4; deferred smem reduction
// ============================================================
__global__ __launch_bounds__(256) void scan3_k(
    const float2* __restrict__ Pa, const float2* __restrict__ Pb,
    const float* __restrict__ Bm, const float* __restrict__ Cm,
    const float* __restrict__ Alog, const float* __restrict__ hinit,
    float* __restrict__ ys)
{
    __shared__ float sP[8][32 * 33];
    int warp = (blockIdx.x * blockDim.x + threadIdx.x) >> 5;
    int wl = (threadIdx.x >> 5);
    int lane = threadIdx.x & 31;
    int ch = warp & (CH - 1);
    int d  = (warp >> 6) & (DIN - 1);
    int b  = warp >> 12;
    float aln = -__expf(Alog[d * 32 + lane]) * 1.4426950408889634f;
    long pbase = ((long)(b * 64 + d) << 12) + ch * LC;
    const float4* Pa4 = (const float4*)(Pa + pbase);
    const float2* PbP = Pb + pbase;
    const float*  Bp = Bm + ((long)((b << 12) + ch * LC) << 5) + lane;
    const float*  Cp = Cm + ((long)((b << 12) + ch * LC) << 5) + lane;
    float h = hinit[(warp << 5) + lane];
    float* sp = sP[wl];
#pragma unroll
    for (int half = 0; half < 2; half++) {
#pragma unroll
        for (int j2 = 0; j2 < 16; j2++) {
            int l = half * 32 + 2 * j2;
            float4 pa = Pa4[half * 16 + j2];
            float bv0 = Bp[l << 5];
            float cv0 = Cp[l << 5];
            float bv1 = Bp[(l + 1) << 5];
            float cv1 = Cp[(l + 1) << 5];
            float dA0 = ex2(pa.x * aln);
            h = fmaf(h, dA0, pa.y * bv0);
            sp[(2 * j2) * 33 + lane] = h * cv0;
            float dA1 = ex2(pa.z * aln);
            h = fmaf(h, dA1, pa.w * bv1);
            sp[(2 * j2 + 1) * 33 + lane] = h * cv1;
        }
        __syncwarp();
        float pr = 0.f;
#pragma unroll
        for (int k = 0; k < 32; k++) pr += sp[lane * 33 + k];
        float2 pb = PbP[half * 32 + lane];
        ys[pbase + half * 32 + lane] = (pr + pb.x) * pb.y;
        __syncwarp();
    }
}

// ============================================================
// out_proj: reads ys [b][d][l], writes yimg (b,c,hw)
// ============================================================
__global__ __launch_bounds__(256) void outproj_k(
    const float* __restrict__ ys, const float* __restrict__ Wo,
    float* __restrict__ oimg)
{
    __shared__ float sA[64 * 68];
    __shared__ float sW[32 * 68];
    const int g0 = blockIdx.x * 64;
    const int tid = threadIdx.x;
    const int b = g0 >> 12;
    const int lb = g0 & 4095;

    for (int i = tid; i < 64 * 64; i += 256) {
        int d = i >> 6, l = i & 63;
        sA[l * 68 + d] = ys[((long)(b * 64 + d) << 12) + lb + l];
    }
    for (int i = tid; i < 32 * 64; i += 256) {
        int c = i >> 6, k = i & 63;
        sW[c * 68 + k] = Wo[i];
    }
    __syncthreads();

    const int rg = tid & 31, cg = tid >> 5;
    const int r0 = rg * 2, c0 = cg * 4;
    float acc[2][4];
#pragma unroll
    for (int j = 0; j < 2; j++)
#pragma unroll
        for (int i = 0; i < 4; i++) acc[j][i] = 0.f;
#pragma unroll 4
    for (int k0 = 0; k0 < 64; k0 += 4) {
        float4 a4[2], w4[4];
#pragma unroll
        for (int j = 0; j < 2; j++) a4[j] = *(const float4*)&sA[(r0 + j) * 68 + k0];
#pragma unroll
        for (int i = 0; i < 4; i++) w4[i] = *(const float4*)&sW[(c0 + i) * 68 + k0];
#pragma unroll
        for (int j = 0; j < 2; j++)
#pragma unroll
            for (int i = 0; i < 4; i++) {
                acc[j][i] = fmaf(a4[j].x, w4[i].x, acc[j][i]);
                acc[j][i] = fmaf(a4[j].y, w4[i].y, acc[j][i]);
                acc[j][i] = fmaf(a4[j].z, w4[i].z, acc[j][i]);
                acc[j][i] = fmaf(a4[j].w, w4[i].w, acc[j][i]);
            }
    }
#pragma unroll
    for (int i = 0; i < 4; i++) {
        int c = c0 + i;
#pragma unroll
        for (int j = 0; j < 2; j++)
            oimg[((long)(b * 32 + c) << 12) + lb + r0 + j] = acc[j][i];
    }
}

// ============================================================
extern "C" void kernel_launch(void* const* d_in, const int* in_sizes, int n_in,
                              void* d_out, int out_size)
{
    const float* x        = (const float*)d_in[0];
    const float* conv1_w  = (const float*)d_in[1];
    const float* conv1_b  = (const float*)d_in[2];
    const float* conv2_w  = (const float*)d_in[3];
    const float* conv2_b  = (const float*)d_in[4];
    const float* ln_g     = (const float*)d_in[5];
    const float* ln_b     = (const float*)d_in[6];
    const float* in_proj_w= (const float*)d_in[7];
    const float* conv1d_w = (const float*)d_in[8];
    const float* conv1d_b = (const float*)d_in[9];
    const float* x_proj_w = (const float*)d_in[10];
    const float* dt_proj_w= (const float*)d_in[11];
    const float* dt_proj_b= (const float*)d_in[12];
    const float* A_log    = (const float*)d_in[13];
    const float* Dp       = (const float*)d_in[14];
    const float* out_proj_w=(const float*)d_in[15];
    const float* smooth_w = (const float*)d_in[16];
    const float* smooth_b = (const float*)d_in[17];
    float* out = (float*)d_out;

    float  *t_, *x2_, *B_, *C_, *ys_, *yimg_, *cA_, *cH_, *hinit_;
    float2 *Pa_, *Pb_;
    cudaGetSymbolAddress((void**)&t_,   g_t);
    cudaGetSymbolAddress((void**)&x2_,  g_x2);
    cudaGetSymbolAddress((void**)&B_,   g_Bm);
    cudaGetSymbolAddress((void**)&C_,   g_Cm);
    cudaGetSymbolAddress((void**)&Pa_,  g_Pa);
    cudaGetSymbolAddress((void**)&Pb_,  g_Pb);
    cudaGetSymbolAddress((void**)&ys_,  g_ys);
    cudaGetSymbolAddress((void**)&yimg_,g_yimg);
    cudaGetSymbolAddress((void**)&cA_,  g_cA);
    cudaGetSymbolAddress((void**)&cH_,  g_cH);
    cudaGetSymbolAddress((void**)&hinit_, g_hinit);

    cudaFuncSetAttribute(big_k, cudaFuncAttributeMaxDynamicSharedMemorySize,
                         BIG_SMEM_FLOATS * 4);

    dim3 thr2d(16, 16);
    // R10 conv config (best measured)
    conv3x3_k<32, 64, 4, true, false><<<dim3(2, 2, BATCH * 16), thr2d>>>(x, conv1_w, conv1_b, nullptr, t_);
    conv3x3_k<64, 32, 2, false, true><<<dim3(2, 2, BATCH * 16), thr2d>>>(t_, conv2_w, conv2_b, x, x2_);
    big_k<<<GTOT / 64, 512, BIG_SMEM_FLOATS * 4>>>(x2_, ln_g, ln_b, in_proj_w,
        conv1d_w, conv1d_b, x_proj_w, dt_proj_w, dt_proj_b, Dp, B_, C_, Pa_, Pb_);
    scan1_k<<<BATCH * DIN * CH / 8, 256>>>(Pa_, B_, A_log, cA_, cH_);
    scan2_k<<<BATCH * DIN / 8, 256>>>(cA_, cH_, hinit_);
    scan3_k<<<BATCH * DIN * CH / 8, 256>>>(Pa_, Pb_, B_, C_, A_log, hinit_, ys_);
    outproj_k<<<GTOT / 64, 256>>>(ys_, out_proj_w, yimg_);
    conv3x3_k<32, 32, 2, false, false><<<dim3(2, 2, BATCH * 16), thr2d>>>(yimg_, smooth_w, smooth_b, nullptr, out);
}